// round 13
// baseline (speedup 1.0000x reference)
#include <cuda_runtime.h>

#define B_ 4
#define S_ 4096
#define NT (B_*S_)            // 16384 tokens
#define H_ 2
#define NBIN 128
#define NCHUNK (S_/32)        // 128 warp-chunks per batch
#define WCUT 24.0f            // log2-domain pruning window
#define ALPHA 1.0201415515301256f   // log2(e)/sqrt(D=2)
#define PAD 64                // per-batch tail padding

// ---- scratch (__device__ globals: allocation-free, bss-zeroed) ----
__device__ float4         g_KR[NT];                   // key record: k0,k1,sv,bin(int bits)
__device__ unsigned short g_CNT[B_][NCHUNK][NBIN];    // per-chunk histograms (K1)
__device__ int            g_OFF[B_][NCHUNK][NBIN];    // global scatter offsets (K2)
__device__ int            g_binStart[B_][2*NBIN+1];
__device__ float4         g_Q[NT*H_];                 // p0,p1,-M, packed(lo|span<<8)
__device__ float4         g_SK [B_][(2*S_+PAD)/2];    // sorted keys, 2/float4, duplicated
__device__ float2         g_SSV[B_][(2*S_+PAD)/2];    // sorted s_v, 2/float2, duplicated

// Monotone angle surrogate ("diamond angle"): bin in [0, NBIN). No trig.
__device__ __forceinline__ int dbin(float xx, float yy)
{
    float ax = fabsf(xx), ay = fabsf(yy);
    float t = ay / (ax + ay + 1e-30f);                // [0,1]
    float a = (xx >= 0.f) ? ((yy >= 0.f) ? t : 4.f - t)
                          : ((yy >= 0.f) ? 2.f - t : 2.f + t);   // [0,4)
    int bn = (int)(a * 32.f);
    return min(max(bn, 0), NBIN-1);
}

// ---------------------------------------------------------------------------
// K1: grid-wide prep, thread-parallel. Key records (+bin) and per-chunk
// histograms (warp-match, deterministic); per-(q,h) window bin range via
// rotating p by +-dmax (cos dmax = 1 - W/M) — no atan/acos.
// ---------------------------------------------------------------------------
__global__ void __launch_bounds__(128) prep_kernel(
    const float* __restrict__ x, const float* __restrict__ freqs,
    const float* __restrict__ qkv, const float* __restrict__ vvec,
    const float* __restrict__ qu,  const float* __restrict__ ku)
{
    int i = blockIdx.x * 128 + threadIdx.x;            // token id
    int s = i & (S_ - 1);
    int b = i >> 12;
    int lane = threadIdx.x & 31;

    const float* xp = x + i*5;
    float a = 0.f, av = 0.f;
#pragma unroll
    for (int j = 0; j < 5; j++) {
        float xv = xp[j];
        a  = fmaf(xv, qkv[j],  a);
        av = fmaf(xv, vvec[j], av);
    }
    float cc, sn;
    sincosf(freqs[s], &sn, &cc);

    // key: rmsnorm(D=2) + rope
    float ku0 = ku[0], ku1 = ku[1];
    float mk   = 0.5f * (ku0*ku0 + ku1*ku1);
    float invk = rsqrtf(fmaf(a*a, mk, 1e-6f));
    float gk   = 16.f * a * invk;
    float kn0 = gk*ku0, kn1 = gk*ku1;
    float k0 = kn0*cc - kn1*sn;
    float k1 = kn0*sn + kn1*cc;
    int bin = dbin(k0, k1);
    g_KR[i] = make_float4(k0, k1, av, __int_as_float(bin));

    // per-chunk histogram via warp match (chunk = 32 consecutive tokens)
    int c = s >> 5;
    unsigned mask = __match_any_sync(0xffffffffu, bin);
    int rank = __popc(mask & ((1u << lane) - 1u));
    if (rank == 0) g_CNT[b][c][bin] = (unsigned short)__popc(mask);

    // queries, both heads: p, -M, window bin range via vector rotation
#pragma unroll
    for (int h = 0; h < 2; h++) {
        float u0 = qu[2*h], u1 = qu[2*h+1];
        float mq  = 0.5f * (u0*u0 + u1*u1);
        float inv = rsqrtf(fmaf(a*a, mq, 1e-6f));
        float gq  = 16.f * a * inv;
        float qn0 = gq*u0, qn1 = gq*u1;
        float p0 = ALPHA * (qn0*cc - qn1*sn);
        float p1 = ALPHA * (qn0*sn + qn1*cc);
        float M  = sqrtf(p0*p0 + p1*p1) * 22.627417f;   // |k| <= 16*sqrt(2)

        int lo, span;
        float cd = 1.f - WCUT / M;                      // cos(dmax); M=0 -> -inf
        if (!(cd > -0.9f)) {                            // wide/full window (rare)
            lo = 0; span = NBIN;
        } else {
            float sd = sqrtf(fmaxf(1.f - cd*cd, 0.f));  // sin(dmax)
            float vlx = fmaf(p0, cd,  p1*sd), vly = fmaf(p1, cd, -p0*sd);
            float vhx = fmaf(p0, cd, -p1*sd), vhy = fmaf(p1, cd,  p0*sd);
            lo = dbin(vlx, vly);
            int hi = dbin(vhx, vhy);
            span = hi - lo; if (span < 0) span += NBIN;
        }
        g_Q[i*2 + h] = make_float4(p0, p1, -M,
                                   __uint_as_float((unsigned)lo | ((unsigned)span << 8)));
    }
}

// ---------------------------------------------------------------------------
// K2: per-batch scans only. Writes ALL of g_OFF + binStart (deterministic).
// ---------------------------------------------------------------------------
__global__ void __launch_bounds__(512) scan_kernel()
{
    __shared__ int pg[4][NBIN];
    __shared__ int binTot[NBIN];
    __shared__ int bs_s[NBIN+1];

    int b = blockIdx.x, tid = threadIdx.x, lane = tid & 31;

    {
        int bin = tid & 127, g = tid >> 7;
        int s = 0;
#pragma unroll 8
        for (int c = g*32; c < g*32 + 32; c++) s += g_CNT[b][c][bin];
        pg[g][bin] = s;
    }
    __syncthreads();
    if (tid < NBIN) {
        int e = 0;
#pragma unroll
        for (int g = 0; g < 4; g++) { int v = pg[g][tid]; pg[g][tid] = e; e += v; }
        binTot[tid] = e;
    }
    __syncthreads();
    if (tid < 32) {
        int v0 = binTot[4*lane], v1 = binTot[4*lane+1],
            v2 = binTot[4*lane+2], v3 = binTot[4*lane+3];
        int sum = v0 + v1 + v2 + v3;
        int run = sum;
#pragma unroll
        for (int o = 1; o < 32; o <<= 1) {
            int n = __shfl_up_sync(0xffffffffu, run, o);
            if (lane >= o) run += n;
        }
        int excl = run - sum;
        bs_s[4*lane]   = excl;
        bs_s[4*lane+1] = excl + v0;
        bs_s[4*lane+2] = excl + v0 + v1;
        bs_s[4*lane+3] = excl + v0 + v1 + v2;
        if (lane == 31) bs_s[NBIN] = run;
    }
    __syncthreads();
    {
        int bin = tid & 127, g = tid >> 7;
        int base = bs_s[bin] + pg[g][bin];
#pragma unroll 8
        for (int c = g*32; c < g*32 + 32; c++) {
            int v = g_CNT[b][c][bin];
            g_OFF[b][c][bin] = base;
            base += v;
        }
    }
    if (tid <= 2*NBIN)
        g_binStart[b][tid] = (tid <= NBIN) ? bs_s[tid] : bs_s[tid-NBIN] + S_;
}

// ---------------------------------------------------------------------------
// K3: grid-wide deterministic scatter. Bin read from record; rank via warp
// match; both duplicated copies written.
// ---------------------------------------------------------------------------
__global__ void __launch_bounds__(128) scatter_kernel()
{
    int lane = threadIdx.x & 31;
    int W = blockIdx.x * 4 + (threadIdx.x >> 5);       // global chunk 0..511
    int b = W >> 7, c = W & 127;
    int i = b*S_ + c*32 + lane;
    float4 r = g_KR[i];
    int bin = __float_as_int(r.w);
    unsigned mask = __match_any_sync(0xffffffffu, bin);
    int rank = __popc(mask & ((1u << lane) - 1u));
    int pos = g_OFF[b][c][bin] + rank;
    float2* sk = (float2*)g_SK[b];
    float*  sv = (float*)g_SSV[b];
    float2 kv = make_float2(r.x, r.y);
    sk[pos]      = kv;
    sk[pos + S_] = kv;
    sv[pos]      = r.z;
    sv[pos + S_] = r.z;
}

// ---------------------------------------------------------------------------
// K4: attention, 2 keys/lane, PREDICATE-FREE accumulation.
// Correctness: keys in [s1, s0a+64*trips) lie in bins past the window edge
// => score-M < -WCUT => e < 2^-24 (legit negligible terms). Since
// s1 <= s0a+S_ and 64 | S_, reads never exceed one circle (no double count)
// and never leave the duplicated table.
// ---------------------------------------------------------------------------
__global__ void __launch_bounds__(256) attn_kernel(
    const float* __restrict__ ov, const float* __restrict__ uv,
    const float* __restrict__ ou, float* __restrict__ out)
{
    __shared__ float s_r[8];
    int wid  = threadIdx.x >> 5;
    int lane = threadIdx.x & 31;
    int w = blockIdx.x * 8 + wid;                      // (q,h) id
    int q = w >> 1;
    int b = q >> 12;

    float4 Q = g_Q[w];
    float p0 = Q.x, p1 = Q.y, nM = Q.z;
    unsigned pk = __float_as_uint(Q.w);
    int lo = (int)(pk & 255u), span = (int)(pk >> 8);

    const int* bs = g_binStart[b];
    int s0  = bs[lo];
    int s0a = s0 & ~63;
    int s1  = (span >= NBIN) ? (s0a + S_) : min(bs[lo + span + 1], s0a + S_);
    int trips = (s1 - s0a + 63) >> 6;

    const float4* __restrict__ sk4 = g_SK[b];
    const float2* __restrict__ sv2 = g_SSV[b];

    float den = 0.f, num = 0.f;
    int p = (s0a >> 1) + lane;                         // pair index
#pragma unroll 2
    for (int t = 0; t < trips; t++, p += 32) {
        float4 kv = sk4[p];
        float2 sv = sv2[p];
        float scA = fmaf(p0, kv.x, fmaf(p1, kv.y, nM));  // <= 0
        float scB = fmaf(p0, kv.z, fmaf(p1, kv.w, nM));
        float eA, eB;
        asm("ex2.approx.ftz.f32 %0, %1;" : "=f"(eA) : "f"(scA));
        asm("ex2.approx.ftz.f32 %0, %1;" : "=f"(eB) : "f"(scB));
        den += eA;
        num = fmaf(eA, sv.x, num);
        den += eB;
        num = fmaf(eB, sv.y, num);
    }
#pragma unroll
    for (int o = 16; o; o >>= 1) {
        den += __shfl_xor_sync(0xffffffffu, den, o);
        num += __shfl_xor_sync(0xffffffffu, num, o);
    }
    if (lane == 0) s_r[wid] = num / den;
    __syncthreads();

    // even-head warps write the query's 5 outputs
    if (!(w & 1) && lane < 5) {
        float C0 = uv[0]*ov[0] + uv[1]*ov[1];
        float C1 = uv[0]*ov[2] + uv[1]*ov[3];
        float so = s_r[wid]*C0 + s_r[wid+1]*C1;
        out[q*5 + lane] = so * ou[lane];
    }
}

extern "C" void kernel_launch(void* const* d_in, const int* in_sizes, int n_in,
                              void* d_out, int out_size)
{
    const float* x     = (const float*)d_in[0];
    const float* freqs = (const float*)d_in[1];
    const float* qkv   = (const float*)d_in[2];
    const float* vv    = (const float*)d_in[3];
    const float* ov    = (const float*)d_in[4];
    const float* uv    = (const float*)d_in[5];
    const float* qu    = (const float*)d_in[6];
    const float* ku    = (const float*)d_in[7];
    const float* ou    = (const float*)d_in[8];

    prep_kernel   <<<NT/128, 128>>>(x, freqs, qkv, vv, qu, ku);
    scan_kernel   <<<B_, 512>>>();
    scatter_kernel<<<NT/32/4, 128>>>();
    attn_kernel   <<<NT*H_/8, 256>>>(ov, uv, ou, (float*)d_out);
}

// round 14
// speedup vs baseline: 1.0051x; 1.0051x over previous
#include <cuda_runtime.h>

#define B_ 4
#define S_ 4096
#define NT (B_*S_)            // 16384 tokens
#define H_ 2
#define NBIN 128
#define NCHUNK (S_/32)        // 128 warp-chunks per batch
#define WCUT 24.0f            // log2-domain pruning window
#define ALPHA 1.0201415515301256f   // log2(e)/sqrt(D=2)
#define PAD 64                // per-batch tail padding

// ---- scratch (__device__ globals: allocation-free, bss-zeroed) ----
__device__ float2         g_CS[S_];                   // (cos,sin) per position
__device__ float4         g_KR[NT];                   // key record: k0,k1,sv,bin(int bits)
__device__ unsigned short g_CNT[B_][NCHUNK][NBIN];    // per-chunk histograms (K1)
__device__ int            g_OFF[B_][NCHUNK][NBIN];    // global scatter offsets (K2)
__device__ int            g_binStart[B_][2*NBIN+1];
__device__ float4         g_Q[NT*H_];                 // p0,p1,-M, packed(lo|span<<8)
__device__ float4         g_SK [B_][(2*S_+PAD)/2];    // sorted keys, 2/float4, duplicated
__device__ float2         g_SSV[B_][(2*S_+PAD)/2];    // sorted s_v, 2/float2, duplicated

// Monotone angle surrogate ("diamond angle"): bin in [0, NBIN). No trig.
__device__ __forceinline__ int dbin(float xx, float yy)
{
    float ax = fabsf(xx), ay = fabsf(yy);
    float t = ay / (ax + ay + 1e-30f);                // [0,1]
    float a = (xx >= 0.f) ? ((yy >= 0.f) ? t : 4.f - t)
                          : ((yy >= 0.f) ? 2.f - t : 2.f + t);   // [0,4)
    int bn = (int)(a * 32.f);
    return min(max(bn, 0), NBIN-1);
}

// ---------------------------------------------------------------------------
// K0: tabulate RoPE cos/sin once per position (4096 distinct, not 16384).
// __sincosf: |err| ~ 2^-21 for |x| < 100 — far below the 1e-3 tolerance.
// ---------------------------------------------------------------------------
__global__ void __launch_bounds__(128) cs_kernel(const float* __restrict__ freqs)
{
    int s = blockIdx.x * 128 + threadIdx.x;
    float cc, sn;
    __sincosf(freqs[s], &sn, &cc);
    g_CS[s] = make_float2(cc, sn);
}

// ---------------------------------------------------------------------------
// K1: grid-wide prep, thread-parallel, trig-free (reads g_CS). Key records
// (+bin) and per-chunk histograms (warp-match, deterministic); per-(q,h)
// window bin range via rotating p by +-dmax (cos dmax = 1 - W/M).
// ---------------------------------------------------------------------------
__global__ void __launch_bounds__(128) prep_kernel(
    const float* __restrict__ x,
    const float* __restrict__ qkv, const float* __restrict__ vvec,
    const float* __restrict__ qu,  const float* __restrict__ ku)
{
    int i = blockIdx.x * 128 + threadIdx.x;            // token id
    int s = i & (S_ - 1);
    int b = i >> 12;
    int lane = threadIdx.x & 31;

    const float* xp = x + i*5;
    float a = 0.f, av = 0.f;
#pragma unroll
    for (int j = 0; j < 5; j++) {
        float xv = xp[j];
        a  = fmaf(xv, qkv[j],  a);
        av = fmaf(xv, vvec[j], av);
    }
    float2 cs = g_CS[s];
    float cc = cs.x, sn = cs.y;

    // key: rmsnorm(D=2) + rope
    float ku0 = ku[0], ku1 = ku[1];
    float mk   = 0.5f * (ku0*ku0 + ku1*ku1);
    float invk = rsqrtf(fmaf(a*a, mk, 1e-6f));
    float gk   = 16.f * a * invk;
    float kn0 = gk*ku0, kn1 = gk*ku1;
    float k0 = kn0*cc - kn1*sn;
    float k1 = kn0*sn + kn1*cc;
    int bin = dbin(k0, k1);
    g_KR[i] = make_float4(k0, k1, av, __int_as_float(bin));

    // per-chunk histogram via warp match (chunk = 32 consecutive tokens)
    int c = s >> 5;
    unsigned mask = __match_any_sync(0xffffffffu, bin);
    int rank = __popc(mask & ((1u << lane) - 1u));
    if (rank == 0) g_CNT[b][c][bin] = (unsigned short)__popc(mask);

    // queries, both heads: p, -M, window bin range via vector rotation
#pragma unroll
    for (int h = 0; h < 2; h++) {
        float u0 = qu[2*h], u1 = qu[2*h+1];
        float mq  = 0.5f * (u0*u0 + u1*u1);
        float inv = rsqrtf(fmaf(a*a, mq, 1e-6f));
        float gq  = 16.f * a * inv;
        float qn0 = gq*u0, qn1 = gq*u1;
        float p0 = ALPHA * (qn0*cc - qn1*sn);
        float p1 = ALPHA * (qn0*sn + qn1*cc);
        float M  = sqrtf(p0*p0 + p1*p1) * 22.627417f;   // |k| <= 16*sqrt(2)

        int lo, span;
        float cd = 1.f - WCUT / M;                      // cos(dmax); M=0 -> -inf
        if (!(cd > -0.9f)) {                            // wide/full window (rare)
            lo = 0; span = NBIN;
        } else {
            float sd = sqrtf(fmaxf(1.f - cd*cd, 0.f));  // sin(dmax)
            float vlx = fmaf(p0, cd,  p1*sd), vly = fmaf(p1, cd, -p0*sd);
            float vhx = fmaf(p0, cd, -p1*sd), vhy = fmaf(p1, cd,  p0*sd);
            lo = dbin(vlx, vly);
            int hi = dbin(vhx, vhy);
            span = hi - lo; if (span < 0) span += NBIN;
        }
        g_Q[i*2 + h] = make_float4(p0, p1, -M,
                                   __uint_as_float((unsigned)lo | ((unsigned)span << 8)));
    }
}

// ---------------------------------------------------------------------------
// K2: per-batch scans only. Writes ALL of g_OFF + binStart (deterministic).
// ---------------------------------------------------------------------------
__global__ void __launch_bounds__(512) scan_kernel()
{
    __shared__ int pg[4][NBIN];
    __shared__ int binTot[NBIN];
    __shared__ int bs_s[NBIN+1];

    int b = blockIdx.x, tid = threadIdx.x, lane = tid & 31;

    {
        int bin = tid & 127, g = tid >> 7;
        int s = 0;
#pragma unroll 8
        for (int c = g*32; c < g*32 + 32; c++) s += g_CNT[b][c][bin];
        pg[g][bin] = s;
    }
    __syncthreads();
    if (tid < NBIN) {
        int e = 0;
#pragma unroll
        for (int g = 0; g < 4; g++) { int v = pg[g][tid]; pg[g][tid] = e; e += v; }
        binTot[tid] = e;
    }
    __syncthreads();
    if (tid < 32) {
        int v0 = binTot[4*lane], v1 = binTot[4*lane+1],
            v2 = binTot[4*lane+2], v3 = binTot[4*lane+3];
        int sum = v0 + v1 + v2 + v3;
        int run = sum;
#pragma unroll
        for (int o = 1; o < 32; o <<= 1) {
            int n = __shfl_up_sync(0xffffffffu, run, o);
            if (lane >= o) run += n;
        }
        int excl = run - sum;
        bs_s[4*lane]   = excl;
        bs_s[4*lane+1] = excl + v0;
        bs_s[4*lane+2] = excl + v0 + v1;
        bs_s[4*lane+3] = excl + v0 + v1 + v2;
        if (lane == 31) bs_s[NBIN] = run;
    }
    __syncthreads();
    {
        int bin = tid & 127, g = tid >> 7;
        int base = bs_s[bin] + pg[g][bin];
#pragma unroll 8
        for (int c = g*32; c < g*32 + 32; c++) {
            int v = g_CNT[b][c][bin];
            g_OFF[b][c][bin] = base;
            base += v;
        }
    }
    if (tid <= 2*NBIN)
        g_binStart[b][tid] = (tid <= NBIN) ? bs_s[tid] : bs_s[tid-NBIN] + S_;
}

// ---------------------------------------------------------------------------
// K3: grid-wide deterministic scatter. Bin read from record; rank via warp
// match; both duplicated copies written.
// ---------------------------------------------------------------------------
__global__ void __launch_bounds__(128) scatter_kernel()
{
    int lane = threadIdx.x & 31;
    int W = blockIdx.x * 4 + (threadIdx.x >> 5);       // global chunk 0..511
    int b = W >> 7, c = W & 127;
    int i = b*S_ + c*32 + lane;
    float4 r = g_KR[i];
    int bin = __float_as_int(r.w);
    unsigned mask = __match_any_sync(0xffffffffu, bin);
    int rank = __popc(mask & ((1u << lane) - 1u));
    int pos = g_OFF[b][c][bin] + rank;
    float2* sk = (float2*)g_SK[b];
    float*  sv = (float*)g_SSV[b];
    float2 kv = make_float2(r.x, r.y);
    sk[pos]      = kv;
    sk[pos + S_] = kv;
    sv[pos]      = r.z;
    sv[pos + S_] = r.z;
}

// ---------------------------------------------------------------------------
// K4: attention, 2 keys/lane, predicate-free, unroll 4 for MLP.
// Correctness: keys in [s1, s0a+64*trips) lie past the window edge =>
// score-M < -WCUT => e < 2^-24 (legit negligible terms). s1 <= s0a+S_ and
// 64 | S_ => reads never exceed one circle nor leave the duplicated table.
// ---------------------------------------------------------------------------
__global__ void __launch_bounds__(256) attn_kernel(
    const float* __restrict__ ov, const float* __restrict__ uv,
    const float* __restrict__ ou, float* __restrict__ out)
{
    __shared__ float s_r[8];
    int wid  = threadIdx.x >> 5;
    int lane = threadIdx.x & 31;
    int w = blockIdx.x * 8 + wid;                      // (q,h) id
    int q = w >> 1;
    int b = q >> 12;

    float4 Q = g_Q[w];
    float p0 = Q.x, p1 = Q.y, nM = Q.z;
    unsigned pk = __float_as_uint(Q.w);
    int lo = (int)(pk & 255u), span = (int)(pk >> 8);

    const int* bs = g_binStart[b];
    int s0  = bs[lo];
    int s0a = s0 & ~63;
    int s1  = (span >= NBIN) ? (s0a + S_) : min(bs[lo + span + 1], s0a + S_);
    int trips = (s1 - s0a + 63) >> 6;

    const float4* __restrict__ sk4 = g_SK[b];
    const float2* __restrict__ sv2 = g_SSV[b];

    float den = 0.f, num = 0.f;
    int p = (s0a >> 1) + lane;                         // pair index
#pragma unroll 4
    for (int t = 0; t < trips; t++, p += 32) {
        float4 kv = sk4[p];
        float2 sv = sv2[p];
        float scA = fmaf(p0, kv.x, fmaf(p1, kv.y, nM));  // <= 0
        float scB = fmaf(p0, kv.z, fmaf(p1, kv.w, nM));
        float eA, eB;
        asm("ex2.approx.ftz.f32 %0, %1;" : "=f"(eA) : "f"(scA));
        asm("ex2.approx.ftz.f32 %0, %1;" : "=f"(eB) : "f"(scB));
        den += eA;
        num = fmaf(eA, sv.x, num);
        den += eB;
        num = fmaf(eB, sv.y, num);
    }
#pragma unroll
    for (int o = 16; o; o >>= 1) {
        den += __shfl_xor_sync(0xffffffffu, den, o);
        num += __shfl_xor_sync(0xffffffffu, num, o);
    }
    if (lane == 0) s_r[wid] = num / den;
    __syncthreads();

    // even-head warps write the query's 5 outputs
    if (!(w & 1) && lane < 5) {
        float C0 = uv[0]*ov[0] + uv[1]*ov[1];
        float C1 = uv[0]*ov[2] + uv[1]*ov[3];
        float so = s_r[wid]*C0 + s_r[wid+1]*C1;
        out[q*5 + lane] = so * ou[lane];
    }
}

extern "C" void kernel_launch(void* const* d_in, const int* in_sizes, int n_in,
                              void* d_out, int out_size)
{
    const float* x     = (const float*)d_in[0];
    const float* freqs = (const float*)d_in[1];
    const float* qkv   = (const float*)d_in[2];
    const float* vv    = (const float*)d_in[3];
    const float* ov    = (const float*)d_in[4];
    const float* uv    = (const float*)d_in[5];
    const float* qu    = (const float*)d_in[6];
    const float* ku    = (const float*)d_in[7];
    const float* ou    = (const float*)d_in[8];

    cs_kernel     <<<S_/128, 128>>>(freqs);
    prep_kernel   <<<NT/128, 128>>>(x, qkv, vv, qu, ku);
    scan_kernel   <<<B_, 512>>>();
    scatter_kernel<<<NT/32/4, 128>>>();
    attn_kernel   <<<NT*H_/8, 256>>>(ov, uv, ou, (float*)d_out);
}